// round 8
// baseline (speedup 1.0000x reference)
#include <cuda_runtime.h>
#include <cuda_fp16.h>
#include <cstdint>

// ============================================================================
// LearnedClassVectors fused fp16 GEMM (M=65536, K=512, N=768), mma.sync.
// R8: two-kernel split, ZERO-smem GEMM.
//   Evidence: R4/R6/R7 all ~190us with L1TEX ~74% across three different
//   schedules -> L1 throughput bound. Fragment traffic is warp-area-optimal
//   already; the removable part is A's smem staging (LDS+STS+ldmatrix).
//   Fix: expand kernel writes A directly in mma-fragment layout to DRAM
//   (g_Af, 64MB, L2-friendly); GEMM reads fragments with one LDG.128 each.
//   No smem, no barriers, no build ALU in the GEMM mainloop.
// ============================================================================

#define MMA16816F(c, a, b0, b1)                                               \
    asm volatile(                                                             \
        "mma.sync.aligned.m16n8k16.row.col.f32.f16.f16.f32 "                  \
        "{%0, %1, %2, %3}, {%4, %5, %6, %7}, {%8, %9}, {%0, %1, %2, %3};"     \
        : "+f"((c)[0]), "+f"((c)[1]), "+f"((c)[2]), "+f"((c)[3])              \
        : "r"((a).x), "r"((a).y), "r"((a).z), "r"((a).w),                     \
          "r"(b0), "r"(b1))

// ---------------- problem constants ----------------
static constexpr int N_TOTAL = 768;
static constexpr int K_TOTAL = 512;
static constexpr int N_TILES = 6;             // 768 / 128
static constexpr int M_TILES = 512;

// Fragment-native fp16 weights (B): blocks (bn 0..95, bk 0..31), each block
// 8n x 16k as 32 lanes x uint2 = the exact m16n8k16 B fragment:
//   lane l: b0 = {w[n][k0+2j], w[n][k0+2j+1]}, b1 = same at k+8,
//   n = bn*8 + l/4, j = l%4, k0 = bk*16.
__device__ __align__(16) uint2 g_Wf[96 * 32 * 32];

// Fragment-native fp16 activations (A): blocks (bm 0..4095 = patch16-block,
// k16 0..31), 32 lanes x uint4 = the exact m16n8k16 A fragment:
//   lane l: a0 = A[r][K+2j .. +1], a1 = A[r+8][K+2j..], a2 = A[r][K+8+2j..],
//           a3 = A[r+8][K+8+2j..],  r = bm*16 + l/4, j = l%4, K = k16*16.
// A[p][k] = vectors[bucket(x voxel)][k%8] with k/8 = voxel pos (pd,ph,pw).
__device__ __align__(16) uint4 g_Af[4096 * 32 * 32];   // 64 MB

__global__ void __launch_bounds__(256) convert_w_kernel(const float* __restrict__ w)
{
    const int idx = blockIdx.x * 256 + threadIdx.x;     // 0 .. 98303
    const int l   = idx & 31;
    const int blk = idx >> 5;                           // bn*32 + bk
    const int bk  = blk & 31;
    const int bn  = blk >> 5;
    const int n   = bn * 8 + (l >> 2);
    const int k0  = bk * 16 + 2 * (l & 3);
    const float* wr = w + (size_t)n * K_TOTAL + k0;
    __half2 p0 = __floats2half2_rn(wr[0], wr[1]);
    __half2 p1 = __floats2half2_rn(wr[8], wr[9]);
    uint2 v;
    v.x = *reinterpret_cast<uint32_t*>(&p0);
    v.y = *reinterpret_cast<uint32_t*>(&p1);
    g_Wf[idx] = v;
}

// bucket = count(x >= iv_i)  ==  searchsorted(side='right')
static __device__ __forceinline__ int hu_bucket(float v)
{
    int b = 0;
    b += (v >= -1000.0f); b += (v >= -900.0f); b += (v >= -400.0f);
    b += (v >= -100.0f);  b += (v >= -50.0f);  b += (v >= -10.0f);
    b += (v >= 20.0f);    b += (v >= 40.0f);   b += (v >= 60.0f);
    b += (v >= 100.0f);   b += (v >= 800.0f);  b += (v >= 1000.0f);
    return b;
}

// ---------------- expand kernel: x -> A fragments ----------------
// One warp per task (bm, k16). Lane l computes the bucket for
// row bm*16 + (l&15), voxel 2*k16 + (l>>4); 4 shuffles distribute the 32
// (row, voxel) buckets; lutpair smem gives the fp16 pair for slot j = l&3.
__global__ void __launch_bounds__(256) expand_a_kernel(
    const float* __restrict__ x, const float* __restrict__ vectors)
{
    __shared__ uint32_t lutpair[13][4];
    const int tid = threadIdx.x;
    const int lane = tid & 31;
    const int w = tid >> 5;

    if (tid < 52) {
        const int c = tid >> 2, j = tid & 3;
        __half2 p = __floats2half2_rn(vectors[c * 8 + 2 * j],
                                      vectors[c * 8 + 2 * j + 1]);
        lutpair[c][j] = *reinterpret_cast<uint32_t*>(&p);
    }
    __syncthreads();

    const int task = blockIdx.x * 8 + w;   // 0 .. 131071 = bm*32 + k16
    const int k16 = task & 31;
    const int bm  = task >> 5;

    // this lane's (row, voxel)
    const int rr = bm * 16 + (lane & 15);
    const int v  = k16 * 2 + (lane >> 4);
    const int b  = rr >> 15;
    const int s  = rr & 32767;
    const int gd = s >> 10, gh = (s >> 5) & 31, gw = s & 31;
    const int pd = v >> 4, ph = (v >> 2) & 3, pw = v & 3;
    const float xv = __ldg(x + ((size_t)b << 21)
                             + ((size_t)(gd * 4 + pd) << 14)
                             + ((gh * 4 + ph) << 7) + (gw * 4 + pw));
    const int bkt = hu_bucket(xv);

    const int q = lane >> 2;   // fragment row index 0..7
    const int j = lane & 3;
    const int b_r1v0 = __shfl_sync(0xFFFFFFFFu, bkt, q);
    const int b_r2v0 = __shfl_sync(0xFFFFFFFFu, bkt, q + 8);
    const int b_r1v1 = __shfl_sync(0xFFFFFFFFu, bkt, q + 16);
    const int b_r2v1 = __shfl_sync(0xFFFFFFFFu, bkt, q + 24);

    uint4 frag;
    frag.x = lutpair[b_r1v0][j];
    frag.y = lutpair[b_r2v0][j];
    frag.z = lutpair[b_r1v1][j];
    frag.w = lutpair[b_r2v1][j];
    g_Af[(size_t)task * 32 + lane] = frag;
}

// ---------------- GEMM kernel: zero smem, no barriers ----------------
__global__ void __launch_bounds__(256, 2) lcv_gemm_kernel(
    const float* __restrict__ fc_b,     // [768]
    float* __restrict__ out)            // [2,768,32,32,32]
{
    const int tid = threadIdx.x;
    const int lane = tid & 31;
    const int warp = tid >> 5;

    // nt fastest: 6 CTAs sharing an A slice are L2-adjacent
    const int nt = blockIdx.x % N_TILES;
    const int mt = blockIdx.x / N_TILES;
    const int m0 = mt << 7;
    const int n0 = nt << 7;
    const int bidx = m0 >> 15;
    const int s0 = m0 & 32767;

    // warp layout: 2 (M) x 4 (N); warp tile 64 x 32
    const int warp_m = (warp >> 2) * 64;
    const int warp_n = (warp & 3) * 32;

    // A fragments: bm = mt*8 + (warp>>2)*4 + mi; addr (bm*32 + kk)*32 + lane
    const uint4* ap = g_Af + ((size_t)(mt * 8 + (warp >> 2) * 4) * 32) * 32 + lane;
    // B fragments: bn = n0/8 + (warp&3)*4 + ni; addr (bn*32 + kk)*32 + lane
    const uint2* bp = g_Wf + ((size_t)(n0 / 8 + (warp & 3) * 4) * 32) * 32 + lane;

    float acc4[4][4][4];
    #pragma unroll
    for (int mi = 0; mi < 4; mi++)
        #pragma unroll
        for (int ni = 0; ni < 4; ni++)
            #pragma unroll
            for (int k = 0; k < 4; k++) acc4[mi][ni][k] = 0.0f;

    // B prefetch for kk = 0
    uint2 bf[2][4];
    #pragma unroll
    for (int ni = 0; ni < 4; ni++)
        bf[0][ni] = __ldg(bp + (size_t)ni * 1024);

    #pragma unroll 4
    for (int kk = 0; kk < 32; kk++) {
        const int cur = kk & 1;
        // prefetch next B (distance 1; proven adequate R4/R6)
        if (kk + 1 < 32) {
            #pragma unroll
            for (int ni = 0; ni < 4; ni++)
                bf[cur ^ 1][ni] = __ldg(bp + (size_t)ni * 1024 + (size_t)(kk + 1) * 32);
        }
        // A fragments: one LDG.128 each (L1 hits for 3 of 4 sharing warps)
        uint4 af[4];
        #pragma unroll
        for (int mi = 0; mi < 4; mi++)
            af[mi] = __ldg(ap + (size_t)mi * 1024 + (size_t)kk * 32);

        #pragma unroll
        for (int ni = 0; ni < 4; ni++) {
            const uint32_t b0 = bf[cur][ni].x;
            const uint32_t b1 = bf[cur][ni].y;
            #pragma unroll
            for (int mi = 0; mi < 4; mi++)
                MMA16816F(acc4[mi][ni], af[mi], b0, b1);
        }
    }

    // ---------- epilogue ----------
    // fragment c0=(m=l/4, n=2(l%4)), c1=(m, n+1), c2=(m+8, n), c3=(m+8, n+1)
    {
        float* ob = out + (size_t)bidx * N_TOTAL * 32768 + (size_t)s0;
        const int mrow = warp_m + (lane >> 2);
        const int ncol = n0 + warp_n + 2 * (lane & 3);
        #pragma unroll
        for (int mi = 0; mi < 4; mi++) {
            const int m_t = mrow + mi * 16;
            #pragma unroll
            for (int ni = 0; ni < 4; ni++) {
                const int o0 = ncol + ni * 8;
                const float2 bv = *reinterpret_cast<const float2*>(fc_b + o0);
                ob[(size_t)o0 * 32768 + m_t]           = acc4[mi][ni][0] + bv.x;
                ob[(size_t)(o0 + 1) * 32768 + m_t]     = acc4[mi][ni][1] + bv.y;
                ob[(size_t)o0 * 32768 + m_t + 8]       = acc4[mi][ni][2] + bv.x;
                ob[(size_t)(o0 + 1) * 32768 + m_t + 8] = acc4[mi][ni][3] + bv.y;
            }
        }
    }
}

// ---------------- launch ----------------
extern "C" void kernel_launch(void* const* d_in, const int* in_sizes, int n_in,
                              void* d_out, int out_size)
{
    (void)in_sizes; (void)n_in; (void)out_size;
    const float* x       = (const float*)d_in[0];  // [2,1,128,128,128]
    const float* vectors = (const float*)d_in[1];  // [13,8]
    const float* fc_w    = (const float*)d_in[2];  // [768,512]
    const float* fc_b    = (const float*)d_in[3];  // [768]
    float* out = (float*)d_out;                    // [2,768,32,32,32]

    convert_w_kernel<<<96 * 32 * 32 / 256, 256>>>(fc_w);
    expand_a_kernel<<<131072 / 8, 256>>>(x, vectors);
    lcv_gemm_kernel<<<M_TILES * N_TILES, 256>>>(fc_b, out);
}

// round 9
// speedup vs baseline: 1.1528x; 1.1528x over previous
#include <cuda_runtime.h>
#include <cuda_fp16.h>
#include <cstdint>

// ============================================================================
// LearnedClassVectors fused fp16 GEMM (M=65536, K=512, N=768), mma.sync.
// R9: R6 (best, 188.4us) + pre-bucketized voxel classes.
//   Evidence R4/R6/R7/R8: GEMM pinned 184-190us across 4 schedules -> at the
//   mma.sync HMMA plateau. Remaining removable cost inside the hot loop is
//   the bucketize ALU (alu=22.3%) and 16B x loads: precompute all voxel
//   buckets into packed u8 (4.2MB, L2-resident) in a single merged prep
//   kernel (also does fc_w -> fragment fp16), then the GEMM A-build is one
//   uchar4 load + LUT gather per stage.
// ============================================================================

static __device__ __forceinline__ uint32_t smem_u32(const void* p) {
    uint32_t a;
    asm("{ .reg .u64 t; cvta.to.shared.u64 t, %1; cvt.u32.u64 %0, t; }"
        : "=r"(a) : "l"(p));
    return a;
}

#define LDS128(r0, r1, r2, r3, addr) \
    asm volatile("ld.shared.v4.u32 {%0, %1, %2, %3}, [%4];" \
                 : "=r"(r0), "=r"(r1), "=r"(r2), "=r"(r3) : "r"(addr))
#define STS128(r0, r1, r2, r3, addr) \
    asm volatile("st.shared.v4.b32 [%0], {%1, %2, %3, %4};" \
                 :: "r"(addr), "r"(r0), "r"(r1), "r"(r2), "r"(r3) : "memory")

#define LDSM_X4(r0, r1, r2, r3, addr) \
    asm volatile("ldmatrix.sync.aligned.m8n8.x4.shared.b16 {%0, %1, %2, %3}, [%4];" \
                 : "=r"(r0), "=r"(r1), "=r"(r2), "=r"(r3) : "r"(addr))

#define MMA16816S(c, a, b0, b1)                                               \
    asm volatile(                                                             \
        "mma.sync.aligned.m16n8k16.row.col.f32.f16.f16.f32 "                  \
        "{%0, %1, %2, %3}, {%4, %5, %6, %7}, {%8, %9}, {%0, %1, %2, %3};"     \
        : "+f"((c)[0]), "+f"((c)[1]), "+f"((c)[2]), "+f"((c)[3])              \
        : "r"((a)[0]), "r"((a)[1]), "r"((a)[2]), "r"((a)[3]),                 \
          "r"(b0), "r"(b1))

// SW128 swizzle for the A tiles (128B rows)
static __device__ __forceinline__ uint32_t swz(uint32_t base, uint32_t row, uint32_t koff) {
    return base + row * 128u + (koff ^ ((row & 7u) * 16u));
}

// ---------------- problem constants ----------------
static constexpr int N_TOTAL = 768;
static constexpr int K_TOTAL = 512;
static constexpr int N_TILES = 6;             // 768 / 128
static constexpr int M_TILES = 512;

// SMEM: LUT + double-buffered A (B never touches smem)
static constexpr int SMEM_LUT = 0;                    // 13 x 16B fp16 vectors
static constexpr int SMEM_A0  = 1024;                 // 128 x 128B = 16 KB
static constexpr int SMEM_A1  = SMEM_A0 + 16384;
static constexpr int SMEM_BYTES = SMEM_A1 + 16384;    // 33792

// Fragment-native fp16 weights (B): lane l of block (bn,bk):
//   b0 = {w[n][k0+2j], w[n][k0+2j+1]}, b1 = same at k+8,
//   n = bn*8 + l/4, j = l%4, k0 = bk*16.
__device__ __align__(16) uint2 g_Wf[96 * 32 * 32];

// Per-voxel HU bucket, packed u8, same [b,d,h,w] linear layout as x.
__device__ __align__(16) unsigned char g_bkt[2 * 2097152];   // 4 MB

// bucket = count(x >= iv_i)  ==  searchsorted(side='right')
static __device__ __forceinline__ int hu_bucket(float v)
{
    int b = 0;
    b += (v >= -1000.0f); b += (v >= -900.0f); b += (v >= -400.0f);
    b += (v >= -100.0f);  b += (v >= -50.0f);  b += (v >= -10.0f);
    b += (v >= 20.0f);    b += (v >= 40.0f);   b += (v >= 60.0f);
    b += (v >= 100.0f);   b += (v >= 800.0f);  b += (v >= 1000.0f);
    return b;
}

// ---------------- merged prep kernel ----------------
// blocks [0, 384):    fc_w fp32 -> fragment-native fp16 (g_Wf)
// blocks [384, 4480): bucketize x -> g_bkt (4 voxels per thread)
__global__ void __launch_bounds__(256) prep_kernel(
    const float* __restrict__ w, const float* __restrict__ x)
{
    const int tid = threadIdx.x;
    if (blockIdx.x < 384) {
        const int idx = blockIdx.x * 256 + tid;         // 0 .. 98303
        const int l   = idx & 31;
        const int blk = idx >> 5;
        const int bk  = blk & 31;
        const int bn  = blk >> 5;
        const int n   = bn * 8 + (l >> 2);
        const int k0  = bk * 16 + 2 * (l & 3);
        const float* wr = w + (size_t)n * K_TOTAL + k0;
        __half2 p0 = __floats2half2_rn(wr[0], wr[1]);
        __half2 p1 = __floats2half2_rn(wr[8], wr[9]);
        uint2 v;
        v.x = *reinterpret_cast<uint32_t*>(&p0);
        v.y = *reinterpret_cast<uint32_t*>(&p1);
        g_Wf[idx] = v;
    } else {
        const int i = (blockIdx.x - 384) * 256 + tid;   // 0 .. 1048575
        const float4 v = *reinterpret_cast<const float4*>(x + (size_t)i * 4);
        uchar4 b;
        b.x = (unsigned char)hu_bucket(v.x);
        b.y = (unsigned char)hu_bucket(v.y);
        b.z = (unsigned char)hu_bucket(v.z);
        b.w = (unsigned char)hu_bucket(v.w);
        *reinterpret_cast<uchar4*>(g_bkt + (size_t)i * 4) = b;
    }
}

// ---------------- main fused kernel ----------------
__global__ void __launch_bounds__(256, 2) lcv_gemm_kernel(
    const float* __restrict__ vectors,  // [13,8]
    const float* __restrict__ fc_b,     // [768]
    float* __restrict__ out)            // [2,768,32,32,32]
{
    extern __shared__ __align__(1024) char smem[];
    const uint32_t sb = smem_u32(smem);
    const int tid = threadIdx.x;
    const int lane = tid & 31;
    const int warp = tid >> 5;

    // nt fastest so the 6 CTAs sharing a bucket-slice are L2-adjacent
    const int nt = blockIdx.x % N_TILES;
    const int mt = blockIdx.x / N_TILES;
    const int m0 = mt << 7;
    const int n0 = nt << 7;
    const int bidx = m0 >> 15;
    const int s0 = m0 & 32767;
    const int gd = s0 >> 10;
    const int gh0 = (s0 >> 5) & 31;

    // warp layout: 2 (M) x 4 (N); warp tile 64 x 32
    const int warp_m = (warp >> 2) * 64;
    const int warp_n = (warp & 3) * 32;

    // vectors LUT -> fp16 smem (13 rows x 16B)
    if (tid < 104) {
        __half h = __float2half_rn(vectors[tid]);
        *reinterpret_cast<__half*>(smem + SMEM_LUT + (tid >> 3) * 16 + (tid & 7) * 2) = h;
    }

    const uint32_t a_off[2] = {SMEM_A0, SMEM_A1};
    const uint32_t lut_base = sb + SMEM_LUT;

    // A-build mapping: thread owns patch-row r, one ph of the stage pair
    const int r = tid >> 1;
    const int ph_off = tid & 1;
    const int gh = gh0 + (r >> 5);
    const int gw = r & 31;
    // bucket row base for this thread (stage s adds ((s>>1)<<14) + ((s&1)<<8))
    const unsigned char* bkrow = g_bkt + ((size_t)bidx << 21)
                               + (((size_t)gd << 2) << 14)
                               + (((gh << 2) + ph_off) << 7) + (gw << 2);
    const uint32_t a_dst_koff = (uint32_t)(ph_off * 64);

    // A ldmatrix per-lane constants
    const uint32_t a_row_l = (uint32_t)(warp_m + (lane & 7) + ((lane >> 3) & 1) * 8);
    const uint32_t a_kc16  = (uint32_t)((lane >> 4) * 16);

    // B fragment pointer (ni stride 1024 uint2, kk stride 32 uint2)
    const uint2* bp = g_Wf + ((size_t)(n0 / 8 + (warp & 3) * 4) * 32) * 32 + lane;

    float acc4[4][4][4];
    #pragma unroll
    for (int mi = 0; mi < 4; mi++)
        #pragma unroll
        for (int ni = 0; ni < 4; ni++)
            #pragma unroll
            for (int k = 0; k < 4; k++) acc4[mi][ni][k] = 0.0f;

    __syncthreads();   // LUT visible

    #define BKLOAD(s) (*reinterpret_cast<const uchar4*>( \
        bkrow + (((size_t)((s) >> 1)) << 14) + (((s) & 1) << 8)))

    // ---------- prologue: build A(stage 0) ----------
    {
        const uchar4 bq = BKLOAD(0);
        const int bks[4] = {bq.x, bq.y, bq.z, bq.w};
        const uint32_t abase = sb + a_off[0];
        #pragma unroll
        for (int pw = 0; pw < 4; pw++) {
            uint32_t q0, q1, q2, q3;
            LDS128(q0, q1, q2, q3, lut_base + (uint32_t)bks[pw] * 16);
            STS128(q0, q1, q2, q3,
                   swz(abase, (uint32_t)r, a_dst_koff + (uint32_t)(pw * 16)));
        }
        __syncthreads();
    }

    // B prefetch for kk=0
    uint2 bf[2][4];
    #pragma unroll
    for (int ni = 0; ni < 4; ni++)
        bf[0][ni] = __ldg(bp + (size_t)ni * 1024);

    // ---------- main loop: 8 A-stages x 4 k16-steps ----------
    int buf = 0;
    for (int ks = 0; ks < 8; ks++) {
        const bool more = (ks + 1 < 8);
        uchar4 bq;

        // next-stage bucket load early (4B; trivial latency to hide)
        if (more) bq = BKLOAD(ks + 1);

        const uint32_t abase = sb + a_off[buf];
        #pragma unroll
        for (int q = 0; q < 4; q++) {
            const int kk = ks * 4 + q;
            const int cur = kk & 1;
            // prefetch B fragments for kk+1
            if (kk + 1 < 32) {
                #pragma unroll
                for (int ni = 0; ni < 4; ni++)
                    bf[cur ^ 1][ni] = __ldg(bp + (size_t)ni * 1024 + (size_t)(kk + 1) * 32);
            }
            // A fragments for this k16
            const uint32_t koffA = (uint32_t)(q * 32) + a_kc16;
            uint32_t af[4][4];
            #pragma unroll
            for (int mi = 0; mi < 4; mi++) {
                LDSM_X4(af[mi][0], af[mi][1], af[mi][2], af[mi][3],
                        swz(abase, a_row_l + (uint32_t)(mi * 16), koffA));
            }
            #pragma unroll
            for (int ni = 0; ni < 4; ni++) {
                const uint32_t b0 = bf[cur][ni].x;
                const uint32_t b1 = bf[cur][ni].y;
                #pragma unroll
                for (int mi = 0; mi < 4; mi++)
                    MMA16816S(acc4[mi][ni], af[mi], b0, b1);
            }
        }

        // build next A stage from prefetched buckets, flip
        if (more) {
            const int bks[4] = {bq.x, bq.y, bq.z, bq.w};
            const uint32_t anext = sb + a_off[buf ^ 1];
            #pragma unroll
            for (int pw = 0; pw < 4; pw++) {
                uint32_t q0, q1, q2, q3;
                LDS128(q0, q1, q2, q3, lut_base + (uint32_t)bks[pw] * 16);
                STS128(q0, q1, q2, q3,
                       swz(anext, (uint32_t)r, a_dst_koff + (uint32_t)(pw * 16)));
            }
            __syncthreads();
            buf ^= 1;
        }
    }
    #undef BKLOAD

    // ---------- epilogue ----------
    // fragment c0=(m=l/4, n=2(l%4)), c1=(m, n+1), c2=(m+8, n), c3=(m+8, n+1)
    {
        float* ob = out + (size_t)bidx * N_TOTAL * 32768 + (size_t)s0;
        const int mrow = warp_m + (lane >> 2);
        const int ncol = n0 + warp_n + 2 * (lane & 3);
        #pragma unroll
        for (int mi = 0; mi < 4; mi++) {
            const int m_t = mrow + mi * 16;
            #pragma unroll
            for (int ni = 0; ni < 4; ni++) {
                const int o0 = ncol + ni * 8;
                const float2 bv = *reinterpret_cast<const float2*>(fc_b + o0);
                ob[(size_t)o0 * 32768 + m_t]           = acc4[mi][ni][0] + bv.x;
                ob[(size_t)(o0 + 1) * 32768 + m_t]     = acc4[mi][ni][1] + bv.y;
                ob[(size_t)o0 * 32768 + m_t + 8]       = acc4[mi][ni][2] + bv.x;
                ob[(size_t)(o0 + 1) * 32768 + m_t + 8] = acc4[mi][ni][3] + bv.y;
            }
        }
    }
}

// ---------------- launch ----------------
extern "C" void kernel_launch(void* const* d_in, const int* in_sizes, int n_in,
                              void* d_out, int out_size)
{
    (void)in_sizes; (void)n_in; (void)out_size;
    const float* x       = (const float*)d_in[0];  // [2,1,128,128,128]
    const float* vectors = (const float*)d_in[1];  // [13,8]
    const float* fc_w    = (const float*)d_in[2];  // [768,512]
    const float* fc_b    = (const float*)d_in[3];  // [768]
    float* out = (float*)d_out;                    // [2,768,32,32,32]

    cudaFuncSetAttribute(lcv_gemm_kernel,
                         cudaFuncAttributeMaxDynamicSharedMemorySize, SMEM_BYTES);

    prep_kernel<<<384 + 4096, 256>>>(fc_w, x);
    lcv_gemm_kernel<<<M_TILES * N_TILES, 256, SMEM_BYTES>>>(vectors, fc_b, out);
}